// round 14
// baseline (speedup 1.0000x reference)
#include <cuda_runtime.h>
#include <cuda_fp16.h>
#include <math.h>
#include <stdint.h>

#define H 1024
#define NHEADS 16
#define HD 64
#define SEQ 2048
#define BATCH 2
#define ROWS (BATCH*SEQ)   // 4096

// ---------------- scratch (device globals; allocation-free) ----------------
__device__ __half g_xh[ROWS*H];
__device__ __half g_qh[ROWS*H];
__device__ __half g_kh[ROWS*H];
__device__ __half g_vh[ROWS*H];
__device__ __half g_ath[ROWS*H];
__device__ __half g_wqkvh[3*H*H];          // packed 0.125*Wq|Wk|Wv, hi only
__device__ __half g_woh[H*H], g_wol[H*H];  // Wo split (A of Wc GEMM)
__device__ __half g_wath[H*H];             // mean(Ws)^T hi only
__device__ __half g_wch[H*H];              // Wc = Wo @ Wa, hi only
__device__ float g_bqkv[3*H];              // 0.125*bq | bk | bv
__device__ float g_bavg[H];
__device__ float g_bc[H];
__device__ float g_zero[H];                // stays 0

// ---------------------------------------------------------------------------
__device__ __forceinline__ unsigned smaddr(const void* p) {
    return (unsigned)__cvta_generic_to_shared(p);
}
__device__ __forceinline__ void ldsm4(unsigned& r0, unsigned& r1, unsigned& r2,
                                      unsigned& r3, unsigned a) {
    asm volatile("ldmatrix.sync.aligned.m8n8.x4.shared.b16 {%0,%1,%2,%3}, [%4];"
                 : "=r"(r0), "=r"(r1), "=r"(r2), "=r"(r3) : "r"(a));
}
__device__ __forceinline__ void ldsm4t(unsigned& r0, unsigned& r1, unsigned& r2,
                                       unsigned& r3, unsigned a) {
    asm volatile("ldmatrix.sync.aligned.m8n8.x4.trans.shared.b16 {%0,%1,%2,%3}, [%4];"
                 : "=r"(r0), "=r"(r1), "=r"(r2), "=r"(r3) : "r"(a));
}
__device__ __forceinline__ void mma16h(float* c, const unsigned* a, const unsigned* b) {
    asm volatile(
        "mma.sync.aligned.m16n8k16.row.col.f32.f16.f16.f32 "
        "{%0,%1,%2,%3}, {%4,%5,%6,%7}, {%8,%9}, {%0,%1,%2,%3};"
        : "+f"(c[0]), "+f"(c[1]), "+f"(c[2]), "+f"(c[3])
        : "r"(a[0]), "r"(a[1]), "r"(a[2]), "r"(a[3]), "r"(b[0]), "r"(b[1]));
}
__device__ __forceinline__ void cpa16(unsigned dst, const void* src) {
    asm volatile("cp.async.ca.shared.global [%0], [%1], 16;" :: "r"(dst), "l"(src));
}
__device__ __forceinline__ unsigned pack2h(float x0, float x1) {
    __half h0 = __float2half_rn(x0), h1 = __float2half_rn(x1);
    return ((unsigned)__half_as_ushort(h1) << 16) | __half_as_ushort(h0);
}

// ---------------------------------------------------------------------------
// fused prep: x trunc, (0.125Wq)/Wk/Wv trunc (packed), Wo split, bias packing
// ---------------------------------------------------------------------------
__global__ void prep_all(const float* __restrict__ x,
                         const float* __restrict__ Wq, const float* __restrict__ Wk,
                         const float* __restrict__ Wv, const float* __restrict__ Wo,
                         const float* __restrict__ bq, const float* __restrict__ bk,
                         const float* __restrict__ bv, const float* __restrict__ bs)
{
    int i = blockIdx.x * 256 + threadIdx.x;
    if (i < ROWS*H) g_xh[i] = __float2half_rn(x[i]);
    if (i < H*H) {
        g_wqkvh[i]         = __float2half_rn(Wq[i] * 0.125f);
        g_wqkvh[H*H + i]   = __float2half_rn(Wk[i]);
        g_wqkvh[2*H*H + i] = __float2half_rn(Wv[i]);
        float w = Wo[i];
        __half h = __float2half_rn(w);
        g_woh[i] = h;
        g_wol[i] = __float2half_rn(w - __half2float(h));
    }
    if (i < H) {
        g_bqkv[i]       = bq[i] * 0.125f;
        g_bqkv[H + i]   = bk[i];
        g_bqkv[2*H + i] = bv[i];
        g_bavg[i] = (bs[i] + bs[i + H] + bs[i + 2*H]) * (1.0f/3.0f);
    }
}
// WaT[h][j] = mean_n Ws[n][j][h], hi only
__global__ void avgT_split(const float* __restrict__ Ws)
{
    __shared__ float tile[32][33];
    int j0 = blockIdx.x * 32, h0 = blockIdx.y * 32;
    int tx = threadIdx.x, ty = threadIdx.y;
    #pragma unroll
    for (int dy = 0; dy < 32; dy += 8) {
        int j = j0 + ty + dy, h = h0 + tx;
        tile[ty + dy][tx] = (Ws[j*H + h] + Ws[H*H + j*H + h] + Ws[2*H*H + j*H + h])
                            * (1.0f/3.0f);
    }
    __syncthreads();
    #pragma unroll
    for (int dy = 0; dy < 32; dy += 8) {
        int h = h0 + ty + dy, j = j0 + tx;
        g_wath[h*H + j] = __float2half_rn(tile[tx][ty + dy]);
    }
}
// bc[g] = Wo[g,:] . bavg + bo[g]; 4 accumulators for MLP
__global__ void bc_kernel(const float* __restrict__ Wo, const float* __restrict__ bo)
{
    int g = blockIdx.x * 8 + (threadIdx.x >> 5);
    int lane = threadIdx.x & 31;
    const float* wr = Wo + (size_t)g * H;
    float s0 = 0.f, s1 = 0.f, s2 = 0.f, s3 = 0.f;
    #pragma unroll
    for (int j = 0; j < H; j += 128) {
        s0 += wr[j + lane]      * g_bavg[j + lane];
        s1 += wr[j + lane + 32] * g_bavg[j + lane + 32];
        s2 += wr[j + lane + 64] * g_bavg[j + lane + 64];
        s3 += wr[j + lane + 96] * g_bavg[j + lane + 96];
    }
    float s = (s0 + s1) + (s2 + s3);
    #pragma unroll
    for (int o = 16; o; o >>= 1) s += __shfl_xor_sync(0xffffffffu, s, o);
    if (lane == 0) g_bc[g] = s + bo[g];
}

// ---------------------------------------------------------------------------
// GEMM: C = A[M,K] @ Bhi[N,K]^T + bias.  AP = A passes (1: hi, 2: hi+lo).
// BM=BN=128, BK=64, 256 thr, 2-stage cp.async pipeline, (AP+1) arrays/stage.
// Row stride 36 words (64 halfs + pad). OUTMODE 0: fp32 C. 1: fp16 Ohi.
// 2: QKV band routing (pure pack).
// ---------------------------------------------------------------------------
#define GSTR 36
#define GARR (128*GSTR)
template<int OUTMODE, int AP>
__global__ __launch_bounds__(256, 2) void gemm_sp(
    const __half* __restrict__ Ahi, const __half* __restrict__ Alo,
    const __half* __restrict__ Bhi,
    const float* __restrict__ bias,
    float* __restrict__ C,
    __half* __restrict__ Ohi,
    __half* __restrict__ Khi,  __half* __restrict__ Vhi,
    int M, int N, int K)
{
    extern __shared__ unsigned gsm[];
    const int NARR = AP + 1;
    const int t = threadIdx.x, lane = t & 31, warp = t >> 5;
    const int wm = (warp >> 2) * 64, wn = (warp & 3) * 32;
    const int m0 = blockIdx.y * 128, n0 = blockIdx.x * 128;

    float acc[16][4];
    #pragma unroll
    for (int i = 0; i < 16; i++)
        #pragma unroll
        for (int j = 0; j < 4; j++) acc[i][j] = 0.0f;

    const int lr = t >> 1, half = t & 1;        // 2 threads/row, 32-half halves
    const size_t arow = (size_t)(m0 + lr) * K + half * 32;
    const size_t brow = (size_t)(n0 + lr) * K + half * 32;
    const int sw = lr * GSTR + half * 16;
    const int NB = K / 64;

    auto fill = [&](int st, int bi) {
        unsigned* B0 = gsm + st * NARR * GARR;
        size_t ko = (size_t)bi * 64;
        #pragma unroll
        for (int i = 0; i < 4; i++) {
            cpa16(smaddr(&B0[0*GARR + sw + i*4]), Ahi + arow + ko + i*8);
            if (AP == 2)
                cpa16(smaddr(&B0[1*GARR + sw + i*4]), Alo + arow + ko + i*8);
            cpa16(smaddr(&B0[(NARR-1)*GARR + sw + i*4]), Bhi + brow + ko + i*8);
        }
        asm volatile("cp.async.commit_group;");
    };

    fill(0, 0);

    for (int bi = 0; bi < NB; bi++) {
        if (bi + 1 < NB) {
            fill((bi + 1) & 1, bi + 1);
            asm volatile("cp.async.wait_group 1;");
        } else {
            asm volatile("cp.async.wait_group 0;");
        }
        __syncthreads();

        unsigned* Ah = gsm + (bi & 1) * NARR * GARR;
        unsigned* Al = Ah + GARR;
        unsigned* Bh = Ah + (NARR-1)*GARR;

        #pragma unroll
        for (int ks = 0; ks < 4; ks++) {
            const int ar = ((lane >> 3) & 1) * 8 + (lane & 7);
            const int aw = ks * 8 + (lane >> 4) * 4;
            unsigned ah[4][4], am[4][4];
            #pragma unroll
            for (int mt = 0; mt < 4; mt++) {
                int r = (wm + mt*16 + ar) * GSTR + aw;
                ldsm4(ah[mt][0], ah[mt][1], ah[mt][2], ah[mt][3], smaddr(&Ah[r]));
                if (AP == 2)
                    ldsm4(am[mt][0], am[mt][1], am[mt][2], am[mt][3], smaddr(&Al[r]));
            }
            const int br = ((lane >> 4) & 1) * 8 + (lane & 7);
            const int bw = ks * 8 + ((lane >> 3) & 1) * 4;
            unsigned bh[2][4];
            #pragma unroll
            for (int np = 0; np < 2; np++) {
                int r = (wn + np*16 + br) * GSTR + bw;
                ldsm4(bh[np][0], bh[np][1], bh[np][2], bh[np][3], smaddr(&Bh[r]));
            }
            #pragma unroll
            for (int mt = 0; mt < 4; mt++)
                #pragma unroll
                for (int nt = 0; nt < 4; nt++) {
                    unsigned* bhp = &bh[nt >> 1][(nt & 1) * 2];
                    mma16h(acc[mt*4+nt], ah[mt], bhp);
                    if (AP == 2) mma16h(acc[mt*4+nt], am[mt], bhp);
                }
        }
        __syncthreads();
    }

    #pragma unroll
    for (int mt = 0; mt < 4; mt++) {
        int row = m0 + wm + mt*16 + (lane >> 2);
        #pragma unroll
        for (int nt = 0; nt < 4; nt++) {
            int col = n0 + wn + nt*8 + (lane & 3) * 2;
            float b0 = __ldg(bias + col), b1 = __ldg(bias + col + 1);
            float* a = acc[mt*4+nt];
            float v00 = a[0] + b0, v01 = a[1] + b1;
            float v10 = a[2] + b0, v11 = a[3] + b1;
            if (OUTMODE == 0) {
                float2 u;
                u.x = v00; u.y = v01; *(float2*)(C + (size_t)row * N + col) = u;
                u.x = v10; u.y = v11; *(float2*)(C + (size_t)(row + 8) * N + col) = u;
            } else if (OUTMODE == 1) {
                *(unsigned*)(Ohi + (size_t)row * N + col)       = pack2h(v00, v01);
                *(unsigned*)(Ohi + (size_t)(row + 8) * N + col) = pack2h(v10, v11);
            } else {
                int which = n0 >> 10;
                int cl = col & 1023;
                __half* dst = (which == 0) ? Ohi : ((which == 1) ? Khi : Vhi);
                *(unsigned*)(dst + (size_t)row * H + cl)       = pack2h(v00, v01);
                *(unsigned*)(dst + (size_t)(row + 8) * H + cl) = pack2h(v10, v11);
            }
        }
    }
}

// ---------------------------------------------------------------------------
// Flash attention, all-fp16, BQ=128, double-buffered KV (R12 proven config).
// 256 threads / 8 warps (16 rows each). Q staged through buffer 1.
// P in registers. fp16 output.
// ---------------------------------------------------------------------------
#define ASTR 36
#define TILE_W (64*ASTR)
#define ATTN_SMEM (4*TILE_W*4)  // 36864 B

__global__ __launch_bounds__(256, 2) void attn_h1(
    const __half* __restrict__ qhi,
    const __half* __restrict__ khi, const __half* __restrict__ vhi,
    __half* __restrict__ athi)
{
    extern __shared__ unsigned smu[];
    unsigned* bufs = smu;

    const int t = threadIdx.x, lane = t & 31, warp = t >> 5;
    const int qb = blockIdx.x, h = blockIdx.y, b = blockIdx.z;
    const int NT = SEQ / 64;

    const int krow = t >> 2, kcb = t & 3;
    const unsigned kd0 = krow * ASTR + kcb * 8;

    // stage Q (128 rows) into buffer 1 (2*TILE_W words)
    {
        const int qrow = t >> 1, qhf = t & 1;
        size_t qoff = ((size_t)(b*SEQ + qb*128 + qrow)) * H + h*HD + qhf*32;
        unsigned d = 2*TILE_W + qrow * ASTR + qhf * 16;
        #pragma unroll
        for (int i = 0; i < 4; i++)
            cpa16(smaddr(&bufs[d + i*4]), qhi + qoff + i*8);
        asm volatile("cp.async.commit_group;");
    }
    // KV tile 0 -> buffer 0
    {
        size_t base = ((size_t)(b*SEQ + krow)) * H + h*HD + kcb*16;
        cpa16(smaddr(&bufs[0*TILE_W + kd0]),     khi + base);
        cpa16(smaddr(&bufs[0*TILE_W + kd0 + 4]), khi + base + 8);
        cpa16(smaddr(&bufs[1*TILE_W + kd0]),     vhi + base);
        cpa16(smaddr(&bufs[1*TILE_W + kd0 + 4]), vhi + base + 8);
        asm volatile("cp.async.commit_group;");
    }

    asm volatile("cp.async.wait_group 1;");
    __syncthreads();

    unsigned qfr[4][4];
    {
        const int ar = warp*16 + ((lane >> 3) & 1) * 8 + (lane & 7);
        #pragma unroll
        for (int ks = 0; ks < 4; ks++) {
            int w = ks * 8 + (lane >> 4) * 4;
            ldsm4(qfr[ks][0], qfr[ks][1], qfr[ks][2], qfr[ks][3],
                  smaddr(&bufs[2*TILE_W + ar*ASTR + w]));
        }
    }
    __syncthreads();

    float o[8][4];
    #pragma unroll
    for (int i = 0; i < 8; i++)
        #pragma unroll
        for (int j = 0; j < 4; j++) o[i][j] = 0.0f;
    float m0 = -1e30f, m1 = -1e30f, l0 = 0.0f, l1 = 0.0f;
    const int r = warp*16 + (lane >> 2);

    for (int kb = 0; kb < NT; kb++) {
        if (kb + 1 < NT) {
            size_t base = ((size_t)(b*SEQ + (kb+1)*64 + krow)) * H + h*HD + kcb*16;
            unsigned* Bn = bufs + ((kb+1) & 1) * 2 * TILE_W;
            cpa16(smaddr(&Bn[0*TILE_W + kd0]),     khi + base);
            cpa16(smaddr(&Bn[0*TILE_W + kd0 + 4]), khi + base + 8);
            cpa16(smaddr(&Bn[1*TILE_W + kd0]),     vhi + base);
            cpa16(smaddr(&Bn[1*TILE_W + kd0 + 4]), vhi + base + 8);
            asm volatile("cp.async.commit_group;");
            asm volatile("cp.async.wait_group 1;");
        } else {
            asm volatile("cp.async.wait_group 0;");
        }
        __syncthreads();

        unsigned* Kh = bufs + (kb & 1) * 2 * TILE_W;
        unsigned* Vh = Kh + TILE_W;

        float s[8][4];
        #pragma unroll
        for (int i = 0; i < 8; i++)
            #pragma unroll
            for (int j = 0; j < 4; j++) s[i][j] = 0.0f;

        #pragma unroll
        for (int ks = 0; ks < 4; ks++) {
            const int br = ((lane >> 4) & 1) * 8 + (lane & 7);
            const int bw = ks * 8 + ((lane >> 3) & 1) * 4;
            unsigned bh[4][4];
            #pragma unroll
            for (int np = 0; np < 4; np++) {
                int rr = (np*16 + br) * ASTR + bw;
                ldsm4(bh[np][0], bh[np][1], bh[np][2], bh[np][3], smaddr(&Kh[rr]));
            }
            #pragma unroll
            for (int nt = 0; nt < 8; nt++)
                mma16h(s[nt], qfr[ks], &bh[nt >> 1][(nt & 1) * 2]);
        }

        float mx0 = -1e30f, mx1 = -1e30f;
        #pragma unroll
        for (int nt = 0; nt < 8; nt++) {
            mx0 = fmaxf(mx0, fmaxf(s[nt][0], s[nt][1]));
            mx1 = fmaxf(mx1, fmaxf(s[nt][2], s[nt][3]));
        }
        mx0 = fmaxf(mx0, __shfl_xor_sync(0xffffffffu, mx0, 1));
        mx0 = fmaxf(mx0, __shfl_xor_sync(0xffffffffu, mx0, 2));
        mx1 = fmaxf(mx1, __shfl_xor_sync(0xffffffffu, mx1, 1));
        mx1 = fmaxf(mx1, __shfl_xor_sync(0xffffffffu, mx1, 2));
        float nm0 = fmaxf(m0, mx0), nm1 = fmaxf(m1, mx1);
        float a0 = __expf(m0 - nm0), a1 = __expf(m1 - nm1);

        float sum0 = 0.0f, sum1 = 0.0f;
        #pragma unroll
        for (int nt = 0; nt < 8; nt++) {
            s[nt][0] = __expf(s[nt][0] - nm0); sum0 += s[nt][0];
            s[nt][1] = __expf(s[nt][1] - nm0); sum0 += s[nt][1];
            s[nt][2] = __expf(s[nt][2] - nm1); sum1 += s[nt][2];
            s[nt][3] = __expf(s[nt][3] - nm1); sum1 += s[nt][3];
        }
        sum0 += __shfl_xor_sync(0xffffffffu, sum0, 1);
        sum0 += __shfl_xor_sync(0xffffffffu, sum0, 2);
        sum1 += __shfl_xor_sync(0xffffffffu, sum1, 1);
        sum1 += __shfl_xor_sync(0xffffffffu, sum1, 2);
        l0 = l0*a0 + sum0;  l1 = l1*a1 + sum1;
        m0 = nm0;           m1 = nm1;
        #pragma unroll
        for (int nt = 0; nt < 8; nt++) {
            o[nt][0] *= a0; o[nt][1] *= a0;
            o[nt][2] *= a1; o[nt][3] *= a1;
        }

        #pragma unroll
        for (int ks = 0; ks < 4; ks++) {
            unsigned ph[4];
            ph[0] = pack2h(s[2*ks][0],   s[2*ks][1]);
            ph[1] = pack2h(s[2*ks][2],   s[2*ks][3]);
            ph[2] = pack2h(s[2*ks+1][0], s[2*ks+1][1]);
            ph[3] = pack2h(s[2*ks+1][2], s[2*ks+1][3]);

            const int vr = ks*16 + ((lane >> 3) & 1) * 8 + (lane & 7);
            unsigned vh[4][4];
            #pragma unroll
            for (int np = 0; np < 4; np++) {
                int vw = np*8 + (lane >> 4) * 4;
                ldsm4t(vh[np][0], vh[np][1], vh[np][2], vh[np][3], smaddr(&Vh[vr*ASTR + vw]));
            }
            #pragma unroll
            for (int nt = 0; nt < 8; nt++)
                mma16h(o[nt], ph, &vh[nt >> 1][(nt & 1) * 2]);
        }
        __syncthreads();
    }

    float inv0 = 1.0f / l0, inv1 = 1.0f / l1;
    size_t gr0 = (size_t)(b*SEQ + qb*128 + r) * H + h*HD;
    size_t gr1 = (size_t)(b*SEQ + qb*128 + r + 8) * H + h*HD;
    int col = (lane & 3) * 2;
    #pragma unroll
    for (int nt = 0; nt < 8; nt++) {
        *(unsigned*)(athi + gr0 + nt*8 + col) = pack2h(o[nt][0]*inv0, o[nt][1]*inv0);
        *(unsigned*)(athi + gr1 + nt*8 + col) = pack2h(o[nt][2]*inv1, o[nt][3]*inv1);
    }
}

// ---------------------------------------------------------------------------
extern "C" void kernel_launch(void* const* d_in, const int* in_sizes, int n_in,
                              void* d_out, int out_size)
{
    const float* x  = (const float*)d_in[0];
    const float* Wq = (const float*)d_in[1];
    const float* bq = (const float*)d_in[2];
    const float* Wk = (const float*)d_in[3];
    const float* bk = (const float*)d_in[4];
    const float* Wv = (const float*)d_in[5];
    const float* bv = (const float*)d_in[6];
    const float* Ws = (const float*)d_in[7];
    const float* bs = (const float*)d_in[8];
    const float* Wo = (const float*)d_in[9];
    const float* bo = (const float*)d_in[10];

    __half *xh, *qh, *kh, *vh, *ath;
    __half *wqkvh, *woh, *wol, *wath, *wch;
    float *bqkvp, *bcp, *zerop;
    cudaGetSymbolAddress((void**)&xh, g_xh);
    cudaGetSymbolAddress((void**)&qh, g_qh);
    cudaGetSymbolAddress((void**)&kh, g_kh);
    cudaGetSymbolAddress((void**)&vh, g_vh);
    cudaGetSymbolAddress((void**)&ath, g_ath);
    cudaGetSymbolAddress((void**)&wqkvh, g_wqkvh);
    cudaGetSymbolAddress((void**)&woh, g_woh); cudaGetSymbolAddress((void**)&wol, g_wol);
    cudaGetSymbolAddress((void**)&wath, g_wath);
    cudaGetSymbolAddress((void**)&wch, g_wch);
    cudaGetSymbolAddress((void**)&bqkvp, g_bqkv);
    cudaGetSymbolAddress((void**)&bcp, g_bc);
    cudaGetSymbolAddress((void**)&zerop, g_zero);

    const int SM1 = 2*2*GARR*4;   // AP=1: 73728 B
    const int SM2 = 2*3*GARR*4;   // AP=2: 110592 B (single-CTA Wc kernel)
    cudaFuncSetAttribute(attn_h1,
                         cudaFuncAttributeMaxDynamicSharedMemorySize, ATTN_SMEM);
    cudaFuncSetAttribute(gemm_sp<0,1>,
                         cudaFuncAttributeMaxDynamicSharedMemorySize, SM1);
    cudaFuncSetAttribute(gemm_sp<1,2>,
                         cudaFuncAttributeMaxDynamicSharedMemorySize, SM2);
    cudaFuncSetAttribute(gemm_sp<2,1>,
                         cudaFuncAttributeMaxDynamicSharedMemorySize, SM1);

    // launch order arranged so ncu's fixed skip lands on attn_h1 (6th launch)
    prep_all<<<(ROWS*H + 255)/256, 256>>>(x, Wq, Wk, Wv, Wo, bq, bk, bv, bs);  // 1
    avgT_split<<<dim3(32, 32), dim3(32, 8)>>>(Ws);                              // 2
    bc_kernel<<<H/8, 256>>>(Wo, bo);                                            // 3

    // Wc = Wo @ mean(Ws): A = Wo split (2-pass), B = WaT hi
    gemm_sp<1,2><<<dim3(8, 8), 256, SM2>>>(
        woh, wol, wath, zerop,
        nullptr, wch, nullptr, nullptr, H, H, H);                               // 4

    // fused QKV (single-pass A): [4096, 3072]
    gemm_sp<2,1><<<dim3(3*H/128, ROWS/128), 256, SM1>>>(
        xh, nullptr, wqkvh, bqkvp,
        nullptr, qh, kh, vh, ROWS, 3*H, H);                                     // 5

    attn_h1<<<dim3(SEQ/128, NHEADS, BATCH), 256, ATTN_SMEM>>>(qh, kh, vh, ath); // 6

    // out = att @ Wc^T + bc (single-pass A)
    gemm_sp<0,1><<<dim3(H/128, ROWS/128), 256, SM1>>>(
        ath, nullptr, wch, bcp,
        (float*)d_out, nullptr, nullptr, nullptr, ROWS, H, H);                  // 7
}

// round 15
// speedup vs baseline: 1.0053x; 1.0053x over previous
#include <cuda_runtime.h>
#include <cuda_fp16.h>
#include <math.h>
#include <stdint.h>

#define H 1024
#define NHEADS 16
#define HD 64
#define SEQ 2048
#define BATCH 2
#define ROWS (BATCH*SEQ)   // 4096

// ---------------- scratch (device globals; allocation-free) ----------------
__device__ __half g_xh[ROWS*H];
__device__ __half g_qh[ROWS*H];
__device__ __half g_kh[ROWS*H];
__device__ __half g_vh[ROWS*H];
__device__ __half g_ath[ROWS*H];
__device__ __half g_wqkvh[3*H*H];          // packed 0.125*Wq|Wk|Wv, hi only
__device__ __half g_woh[H*H], g_wol[H*H];  // Wo split (A of Wc GEMM)
__device__ __half g_wath[H*H];             // mean(Ws)^T hi only
__device__ __half g_wch[H*H];              // Wc = Wo @ Wa, hi only
__device__ float g_bqkv[3*H];              // 0.125*bq | bk | bv
__device__ float g_bavg[H];
__device__ float g_bc[H];

// ---------------------------------------------------------------------------
__device__ __forceinline__ unsigned smaddr(const void* p) {
    return (unsigned)__cvta_generic_to_shared(p);
}
__device__ __forceinline__ void ldsm4(unsigned& r0, unsigned& r1, unsigned& r2,
                                      unsigned& r3, unsigned a) {
    asm volatile("ldmatrix.sync.aligned.m8n8.x4.shared.b16 {%0,%1,%2,%3}, [%4];"
                 : "=r"(r0), "=r"(r1), "=r"(r2), "=r"(r3) : "r"(a));
}
__device__ __forceinline__ void ldsm4t(unsigned& r0, unsigned& r1, unsigned& r2,
                                       unsigned& r3, unsigned a) {
    asm volatile("ldmatrix.sync.aligned.m8n8.x4.trans.shared.b16 {%0,%1,%2,%3}, [%4];"
                 : "=r"(r0), "=r"(r1), "=r"(r2), "=r"(r3) : "r"(a));
}
__device__ __forceinline__ void mma16h(float* c, const unsigned* a, const unsigned* b) {
    asm volatile(
        "mma.sync.aligned.m16n8k16.row.col.f32.f16.f16.f32 "
        "{%0,%1,%2,%3}, {%4,%5,%6,%7}, {%8,%9}, {%0,%1,%2,%3};"
        : "+f"(c[0]), "+f"(c[1]), "+f"(c[2]), "+f"(c[3])
        : "r"(a[0]), "r"(a[1]), "r"(a[2]), "r"(a[3]), "r"(b[0]), "r"(b[1]));
}
__device__ __forceinline__ void cpa16(unsigned dst, const void* src) {
    asm volatile("cp.async.ca.shared.global [%0], [%1], 16;" :: "r"(dst), "l"(src));
}
__device__ __forceinline__ unsigned pack2h(float x0, float x1) {
    __half h0 = __float2half_rn(x0), h1 = __float2half_rn(x1);
    return ((unsigned)__half_as_ushort(h1) << 16) | __half_as_ushort(h0);
}

// ---------------------------------------------------------------------------
// fused prep
// ---------------------------------------------------------------------------
__global__ void prep_all(const float* __restrict__ x,
                         const float* __restrict__ Wq, const float* __restrict__ Wk,
                         const float* __restrict__ Wv, const float* __restrict__ Wo,
                         const float* __restrict__ bq, const float* __restrict__ bk,
                         const float* __restrict__ bv, const float* __restrict__ bs)
{
    int i = blockIdx.x * 256 + threadIdx.x;
    if (i < ROWS*H) g_xh[i] = __float2half_rn(x[i]);
    if (i < H*H) {
        g_wqkvh[i]         = __float2half_rn(Wq[i] * 0.125f);
        g_wqkvh[H*H + i]   = __float2half_rn(Wk[i]);
        g_wqkvh[2*H*H + i] = __float2half_rn(Wv[i]);
        float w = Wo[i];
        __half h = __float2half_rn(w);
        g_woh[i] = h;
        g_wol[i] = __float2half_rn(w - __half2float(h));
    }
    if (i < H) {
        g_bqkv[i]       = bq[i] * 0.125f;
        g_bqkv[H + i]   = bk[i];
        g_bqkv[2*H + i] = bv[i];
        g_bavg[i] = (bs[i] + bs[i + H] + bs[i + 2*H]) * (1.0f/3.0f);
    }
}
__global__ void avgT_split(const float* __restrict__ Ws)
{
    __shared__ float tile[32][33];
    int j0 = blockIdx.x * 32, h0 = blockIdx.y * 32;
    int tx = threadIdx.x, ty = threadIdx.y;
    #pragma unroll
    for (int dy = 0; dy < 32; dy += 8) {
        int j = j0 + ty + dy, h = h0 + tx;
        tile[ty + dy][tx] = (Ws[j*H + h] + Ws[H*H + j*H + h] + Ws[2*H*H + j*H + h])
                            * (1.0f/3.0f);
    }
    __syncthreads();
    #pragma unroll
    for (int dy = 0; dy < 32; dy += 8) {
        int h = h0 + ty + dy, j = j0 + tx;
        g_wath[h*H + j] = __float2half_rn(tile[tx][ty + dy]);
    }
}
__global__ void bc_kernel(const float* __restrict__ Wo, const float* __restrict__ bo)
{
    int g = blockIdx.x * 8 + (threadIdx.x >> 5);
    int lane = threadIdx.x & 31;
    const float* wr = Wo + (size_t)g * H;
    float s0 = 0.f, s1 = 0.f, s2 = 0.f, s3 = 0.f;
    #pragma unroll
    for (int j = 0; j < H; j += 128) {
        s0 += wr[j + lane]      * g_bavg[j + lane];
        s1 += wr[j + lane + 32] * g_bavg[j + lane + 32];
        s2 += wr[j + lane + 64] * g_bavg[j + lane + 64];
        s3 += wr[j + lane + 96] * g_bavg[j + lane + 96];
    }
    float s = (s0 + s1) + (s2 + s3);
    #pragma unroll
    for (int o = 16; o; o >>= 1) s += __shfl_xor_sync(0xffffffffu, s, o);
    if (lane == 0) g_bc[g] = s + bo[g];
}

// ---------------------------------------------------------------------------
// Combined QKV + Wc kernel.  Grid (26, 32):
//   blockIdx.x < 24  -> QKV tile: C = xh @ wqkv^T + bqkv, band-routed fp16.
//   blockIdx.x >= 24 -> Wc tile:  wch = (woh+wol) @ wath^T (2-pass A, no bias).
// BK=32, 2-stage cp.async, 3 smem arrays/stage (A, Alo, B).
// ---------------------------------------------------------------------------
#define GSTR 20
#define GARR (128*GSTR)
#define SM_COMB (2*3*GARR*4)   // 61440 B
__global__ __launch_bounds__(256, 2) void gemm_qkv_wc(
    const __half* __restrict__ xh,  const __half* __restrict__ wqkv,
    const float* __restrict__ bqkv,
    const __half* __restrict__ woh, const __half* __restrict__ wol,
    const __half* __restrict__ wath,
    __half* __restrict__ qh, __half* __restrict__ kh, __half* __restrict__ vh,
    __half* __restrict__ wch)
{
    extern __shared__ unsigned gsm[];
    const int t = threadIdx.x, lane = t & 31, warp = t >> 5;
    const int wm = (warp >> 2) * 64, wn = (warp & 3) * 32;

    const bool isWc = (blockIdx.x >= 24);
    int m0, n0;
    const __half *Ahi, *Alo, *Bhi;
    if (!isWc) {
        m0 = blockIdx.y * 128;  n0 = blockIdx.x * 128;
        Ahi = xh;  Alo = nullptr;  Bhi = wqkv;
    } else {
        int wi = (blockIdx.x - 24) * 32 + blockIdx.y;   // 0..63
        m0 = (wi >> 3) * 128;  n0 = (wi & 7) * 128;
        Ahi = woh;  Alo = wol;  Bhi = wath;
    }

    float acc[16][4];
    #pragma unroll
    for (int i = 0; i < 16; i++)
        #pragma unroll
        for (int j = 0; j < 4; j++) acc[i][j] = 0.0f;

    const int lr = t >> 1, half = t & 1;
    const size_t arow = (size_t)(m0 + lr) * H + half * 16;
    const size_t brow = (size_t)(n0 + lr) * H + half * 16;
    const int sw = lr * GSTR + half * 8;
    const int NB = H / 32;

    auto fill = [&](int st, int bi) {
        unsigned* B0 = gsm + st * 3 * GARR;
        size_t ko = (size_t)bi * 32;
        cpa16(smaddr(&B0[0*GARR + sw]),     Ahi + arow + ko);
        cpa16(smaddr(&B0[0*GARR + sw + 4]), Ahi + arow + ko + 8);
        if (isWc) {
            cpa16(smaddr(&B0[1*GARR + sw]),     Alo + arow + ko);
            cpa16(smaddr(&B0[1*GARR + sw + 4]), Alo + arow + ko + 8);
        }
        cpa16(smaddr(&B0[2*GARR + sw]),     Bhi + brow + ko);
        cpa16(smaddr(&B0[2*GARR + sw + 4]), Bhi + brow + ko + 8);
        asm volatile("cp.async.commit_group;");
    };

    fill(0, 0);

    for (int bi = 0; bi < NB; bi++) {
        if (bi + 1 < NB) {
            fill((bi + 1) & 1, bi + 1);
            asm volatile("cp.async.wait_group 1;");
        } else {
            asm volatile("cp.async.wait_group 0;");
        }
        __syncthreads();

        unsigned* Ah = gsm + (bi & 1) * 3 * GARR;
        unsigned* Al = Ah + GARR;
        unsigned* Bh = Ah + 2*GARR;

        #pragma unroll
        for (int ks = 0; ks < 2; ks++) {
            const int ar = ((lane >> 3) & 1) * 8 + (lane & 7);
            const int aw = ks * 8 + (lane >> 4) * 4;
            unsigned ah[4][4], am[4][4];
            #pragma unroll
            for (int mt = 0; mt < 4; mt++) {
                int r = (wm + mt*16 + ar) * GSTR + aw;
                ldsm4(ah[mt][0], ah[mt][1], ah[mt][2], ah[mt][3], smaddr(&Ah[r]));
                if (isWc)
                    ldsm4(am[mt][0], am[mt][1], am[mt][2], am[mt][3], smaddr(&Al[r]));
            }
            const int br = ((lane >> 4) & 1) * 8 + (lane & 7);
            const int bw = ks * 8 + ((lane >> 3) & 1) * 4;
            unsigned bh[2][4];
            #pragma unroll
            for (int np = 0; np < 2; np++) {
                int r = (wn + np*16 + br) * GSTR + bw;
                ldsm4(bh[np][0], bh[np][1], bh[np][2], bh[np][3], smaddr(&Bh[r]));
            }
            #pragma unroll
            for (int mt = 0; mt < 4; mt++)
                #pragma unroll
                for (int nt = 0; nt < 4; nt++) {
                    unsigned* bhp = &bh[nt >> 1][(nt & 1) * 2];
                    mma16h(acc[mt*4+nt], ah[mt], bhp);
                    if (isWc) mma16h(acc[mt*4+nt], am[mt], bhp);
                }
        }
        __syncthreads();
    }

    #pragma unroll
    for (int mt = 0; mt < 4; mt++) {
        int row = m0 + wm + mt*16 + (lane >> 2);
        #pragma unroll
        for (int nt = 0; nt < 4; nt++) {
            int col = n0 + wn + nt*8 + (lane & 3) * 2;
            float* a = acc[mt*4+nt];
            if (isWc) {
                *(unsigned*)(wch + (size_t)row * H + col)       = pack2h(a[0], a[1]);
                *(unsigned*)(wch + (size_t)(row + 8) * H + col) = pack2h(a[2], a[3]);
            } else {
                float b0 = __ldg(bqkv + col), b1 = __ldg(bqkv + col + 1);
                float v00 = a[0] + b0, v01 = a[1] + b1;
                float v10 = a[2] + b0, v11 = a[3] + b1;
                int which = n0 >> 10;
                int cl = col & 1023;
                __half* dst = (which == 0) ? qh : ((which == 1) ? kh : vh);
                *(unsigned*)(dst + (size_t)row * H + cl)       = pack2h(v00, v01);
                *(unsigned*)(dst + (size_t)(row + 8) * H + cl) = pack2h(v10, v11);
            }
        }
    }
}

// ---------------------------------------------------------------------------
// Final GEMM: out = ath @ wch^T + bc (fp32 out). BK=32, 2-stage, 2 arrays.
// ---------------------------------------------------------------------------
#define SM_FIN (2*2*GARR*4)   // 40960 B
__global__ __launch_bounds__(256, 2) void gemm_fin(
    const __half* __restrict__ Ahi, const __half* __restrict__ Bhi,
    const float* __restrict__ bias, float* __restrict__ C, int M, int N, int K)
{
    extern __shared__ unsigned gsm[];
    const int t = threadIdx.x, lane = t & 31, warp = t >> 5;
    const int wm = (warp >> 2) * 64, wn = (warp & 3) * 32;
    const int m0 = blockIdx.y * 128, n0 = blockIdx.x * 128;

    float acc[16][4];
    #pragma unroll
    for (int i = 0; i < 16; i++)
        #pragma unroll
        for (int j = 0; j < 4; j++) acc[i][j] = 0.0f;

    const int lr = t >> 1, half = t & 1;
    const size_t arow = (size_t)(m0 + lr) * K + half * 16;
    const size_t brow = (size_t)(n0 + lr) * K + half * 16;
    const int sw = lr * GSTR + half * 8;
    const int NB = K / 32;

    auto fill = [&](int st, int bi) {
        unsigned* B0 = gsm + st * 2 * GARR;
        size_t ko = (size_t)bi * 32;
        cpa16(smaddr(&B0[0*GARR + sw]),     Ahi + arow + ko);
        cpa16(smaddr(&B0[0*GARR + sw + 4]), Ahi + arow + ko + 8);
        cpa16(smaddr(&B0[1*GARR + sw]),     Bhi + brow + ko);
        cpa16(smaddr(&B0[1*GARR + sw + 4]), Bhi + brow + ko + 8);
        asm volatile("cp.async.commit_group;");
    };

    fill(0, 0);

    for (int bi = 0; bi < NB; bi++) {
        if (bi + 1 < NB) {
            fill((bi + 1) & 1, bi + 1);
            asm volatile("cp.async.wait_group 1;");
        } else {
            asm volatile("cp.async.wait_group 0;");
        }
        __syncthreads();

        unsigned* Ah = gsm + (bi & 1) * 2 * GARR;
        unsigned* Bh = Ah + GARR;

        #pragma unroll
        for (int ks = 0; ks < 2; ks++) {
            const int ar = ((lane >> 3) & 1) * 8 + (lane & 7);
            const int aw = ks * 8 + (lane >> 4) * 4;
            unsigned ah[4][4];
            #pragma unroll
            for (int mt = 0; mt < 4; mt++) {
                int r = (wm + mt*16 + ar) * GSTR + aw;
                ldsm4(ah[mt][0], ah[mt][1], ah[mt][2], ah[mt][3], smaddr(&Ah[r]));
            }
            const int br = ((lane >> 4) & 1) * 8 + (lane & 7);
            const int bw = ks * 8 + ((lane >> 3) & 1) * 4;
            unsigned bh[2][4];
            #pragma unroll
            for (int np = 0; np < 2; np++) {
                int r = (wn + np*16 + br) * GSTR + bw;
                ldsm4(bh[np][0], bh[np][1], bh[np][2], bh[np][3], smaddr(&Bh[r]));
            }
            #pragma unroll
            for (int mt = 0; mt < 4; mt++)
                #pragma unroll
                for (int nt = 0; nt < 4; nt++)
                    mma16h(acc[mt*4+nt], ah[mt], &bh[nt >> 1][(nt & 1) * 2]);
        }
        __syncthreads();
    }

    #pragma unroll
    for (int mt = 0; mt < 4; mt++) {
        int row = m0 + wm + mt*16 + (lane >> 2);
        #pragma unroll
        for (int nt = 0; nt < 4; nt++) {
            int col = n0 + wn + nt*8 + (lane & 3) * 2;
            float b0 = __ldg(bias + col), b1 = __ldg(bias + col + 1);
            float* a = acc[mt*4+nt];
            float2 u;
            u.x = a[0] + b0; u.y = a[1] + b1;
            *(float2*)(C + (size_t)row * N + col) = u;
            u.x = a[2] + b0; u.y = a[3] + b1;
            *(float2*)(C + (size_t)(row + 8) * N + col) = u;
        }
    }
}

// ---------------------------------------------------------------------------
// Flash attention, all-fp16, BQ=128, double-buffered KV (R12 proven config).
// ---------------------------------------------------------------------------
#define ASTR 36
#define TILE_W (64*ASTR)
#define ATTN_SMEM (4*TILE_W*4)  // 36864 B

__global__ __launch_bounds__(256, 2) void attn_h1(
    const __half* __restrict__ qhi,
    const __half* __restrict__ khi, const __half* __restrict__ vhi,
    __half* __restrict__ athi)
{
    extern __shared__ unsigned smu[];
    unsigned* bufs = smu;

    const int t = threadIdx.x, lane = t & 31, warp = t >> 5;
    const int qb = blockIdx.x, h = blockIdx.y, b = blockIdx.z;
    const int NT = SEQ / 64;

    const int krow = t >> 2, kcb = t & 3;
    const unsigned kd0 = krow * ASTR + kcb * 8;

    {
        const int qrow = t >> 1, qhf = t & 1;
        size_t qoff = ((size_t)(b*SEQ + qb*128 + qrow)) * H + h*HD + qhf*32;
        unsigned d = 2*TILE_W + qrow * ASTR + qhf * 16;
        #pragma unroll
        for (int i = 0; i < 4; i++)
            cpa16(smaddr(&bufs[d + i*4]), qhi + qoff + i*8);
        asm volatile("cp.async.commit_group;");
    }
    {
        size_t base = ((size_t)(b*SEQ + krow)) * H + h*HD + kcb*16;
        cpa16(smaddr(&bufs[0*TILE_W + kd0]),     khi + base);
        cpa16(smaddr(&bufs[0*TILE_W + kd0 + 4]), khi + base + 8);
        cpa16(smaddr(&bufs[1*TILE_W + kd0]),     vhi + base);
        cpa16(smaddr(&bufs[1*TILE_W + kd0 + 4]), vhi + base + 8);
        asm volatile("cp.async.commit_group;");
    }

    asm volatile("cp.async.wait_group 1;");
    __syncthreads();

    unsigned qfr[4][4];
    {
        const int ar = warp*16 + ((lane >> 3) & 1) * 8 + (lane & 7);
        #pragma unroll
        for (int ks = 0; ks < 4; ks++) {
            int w = ks * 8 + (lane >> 4) * 4;
            ldsm4(qfr[ks][0], qfr[ks][1], qfr[ks][2], qfr[ks][3],
                  smaddr(&bufs[2*TILE_W + ar*ASTR + w]));
        }
    }
    __syncthreads();

    float o[8][4];
    #pragma unroll
    for (int i = 0; i < 8; i++)
        #pragma unroll
        for (int j = 0; j < 4; j++) o[i][j] = 0.0f;
    float m0 = -1e30f, m1 = -1e30f, l0 = 0.0f, l1 = 0.0f;
    const int r = warp*16 + (lane >> 2);

    for (int kb = 0; kb < NT; kb++) {
        if (kb + 1 < NT) {
            size_t base = ((size_t)(b*SEQ + (kb+1)*64 + krow)) * H + h*HD + kcb*16;
            unsigned* Bn = bufs + ((kb+1) & 1) * 2 * TILE_W;
            cpa16(smaddr(&Bn[0*TILE_W + kd0]),     khi + base);
            cpa16(smaddr(&Bn[0*TILE_W + kd0 + 4]), khi + base + 8);
            cpa16(smaddr(&Bn[1*TILE_W + kd0]),     vhi + base);
            cpa16(smaddr(&Bn[1*TILE_W + kd0 + 4]), vhi + base + 8);
            asm volatile("cp.async.commit_group;");
            asm volatile("cp.async.wait_group 1;");
        } else {
            asm volatile("cp.async.wait_group 0;");
        }
        __syncthreads();

        unsigned* Kh = bufs + (kb & 1) * 2 * TILE_W;
        unsigned* Vh = Kh + TILE_W;

        float s[8][4];
        #pragma unroll
        for (int i = 0; i < 8; i++)
            #pragma unroll
            for (int j = 0; j < 4; j++) s[i][j] = 0.0f;

        #pragma unroll
        for (int ks = 0; ks < 4; ks++) {
            const int br = ((lane >> 4) & 1) * 8 + (lane & 7);
            const int bw = ks * 8 + ((lane >> 3) & 1) * 4;
            unsigned bh[4][4];
            #pragma unroll
            for (int np = 0; np < 4; np++) {
                int rr = (np*16 + br) * ASTR + bw;
                ldsm4(bh[np][0], bh[np][1], bh[np][2], bh[np][3], smaddr(&Kh[rr]));
            }
            #pragma unroll
            for (int nt = 0; nt < 8; nt++)
                mma16h(s[nt], qfr[ks], &bh[nt >> 1][(nt & 1) * 2]);
        }

        float mx0 = -1e30f, mx1 = -1e30f;
        #pragma unroll
        for (int nt = 0; nt < 8; nt++) {
            mx0 = fmaxf(mx0, fmaxf(s[nt][0], s[nt][1]));
            mx1 = fmaxf(mx1, fmaxf(s[nt][2], s[nt][3]));
        }
        mx0 = fmaxf(mx0, __shfl_xor_sync(0xffffffffu, mx0, 1));
        mx0 = fmaxf(mx0, __shfl_xor_sync(0xffffffffu, mx0, 2));
        mx1 = fmaxf(mx1, __shfl_xor_sync(0xffffffffu, mx1, 1));
        mx1 = fmaxf(mx1, __shfl_xor_sync(0xffffffffu, mx1, 2));
        float nm0 = fmaxf(m0, mx0), nm1 = fmaxf(m1, mx1);
        float a0 = __expf(m0 - nm0), a1 = __expf(m1 - nm1);

        float sum0 = 0.0f, sum1 = 0.0f;
        #pragma unroll
        for (int nt = 0; nt < 8; nt++) {
            s[nt][0] = __expf(s[nt][0] - nm0); sum0 += s[nt][0];
            s[nt][1] = __expf(s[nt][1] - nm0); sum0 += s[nt][1];
            s[nt][2] = __expf(s[nt][2] - nm1); sum1 += s[nt][2];
            s[nt][3] = __expf(s[nt][3] - nm1); sum1 += s[nt][3];
        }
        sum0 += __shfl_xor_sync(0xffffffffu, sum0, 1);
        sum0 += __shfl_xor_sync(0xffffffffu, sum0, 2);
        sum1 += __shfl_xor_sync(0xffffffffu, sum1, 1);
        sum1 += __shfl_xor_sync(0xffffffffu, sum1, 2);
        l0 = l0*a0 + sum0;  l1 = l1*a1 + sum1;
        m0 = nm0;           m1 = nm1;
        #pragma unroll
        for (int nt = 0; nt < 8; nt++) {
            o[nt][0] *= a0; o[nt][1] *= a0;
            o[nt][2] *= a1; o[nt][3] *= a1;
        }

        #pragma unroll
        for (int ks = 0; ks < 4; ks++) {
            unsigned ph[4];
            ph[0] = pack2h(s[2*ks][0],   s[2*ks][1]);
            ph[1] = pack2h(s[2*ks][2],   s[2*ks][3]);
            ph[2] = pack2h(s[2*ks+1][0], s[2*ks+1][1]);
            ph[3] = pack2h(s[2*ks+1][2], s[2*ks+1][3]);

            const int vr = ks*16 + ((lane >> 3) & 1) * 8 + (lane & 7);
            unsigned vh[4][4];
            #pragma unroll
            for (int np = 0; np < 4; np++) {
                int vw = np*8 + (lane >> 4) * 4;
                ldsm4t(vh[np][0], vh[np][1], vh[np][2], vh[np][3], smaddr(&Vh[vr*ASTR + vw]));
            }
            #pragma unroll
            for (int nt = 0; nt < 8; nt++)
                mma16h(o[nt], ph, &vh[nt >> 1][(nt & 1) * 2]);
        }
        __syncthreads();
    }

    float inv0 = 1.0f / l0, inv1 = 1.0f / l1;
    size_t gr0 = (size_t)(b*SEQ + qb*128 + r) * H + h*HD;
    size_t gr1 = (size_t)(b*SEQ + qb*128 + r + 8) * H + h*HD;
    int col = (lane & 3) * 2;
    #pragma unroll
    for (int nt = 0; nt < 8; nt++) {
        *(unsigned*)(athi + gr0 + nt*8 + col) = pack2h(o[nt][0]*inv0, o[nt][1]*inv0);
        *(unsigned*)(athi + gr1 + nt*8 + col) = pack2h(o[nt][2]*inv1, o[nt][3]*inv1);
    }
}

// ---------------------------------------------------------------------------
extern "C" void kernel_launch(void* const* d_in, const int* in_sizes, int n_in,
                              void* d_out, int out_size)
{
    const float* x  = (const float*)d_in[0];
    const float* Wq = (const float*)d_in[1];
    const float* bq = (const float*)d_in[2];
    const float* Wk = (const float*)d_in[3];
    const float* bk = (const float*)d_in[4];
    const float* Wv = (const float*)d_in[5];
    const float* bv = (const float*)d_in[6];
    const float* Ws = (const float*)d_in[7];
    const float* bs = (const float*)d_in[8];
    const float* Wo = (const float*)d_in[9];
    const float* bo = (const float*)d_in[10];

    __half *xh, *qh, *kh, *vh, *ath;
    __half *wqkvh, *woh, *wol, *wath, *wch;
    float *bqkvp, *bcp;
    cudaGetSymbolAddress((void**)&xh, g_xh);
    cudaGetSymbolAddress((void**)&qh, g_qh);
    cudaGetSymbolAddress((void**)&kh, g_kh);
    cudaGetSymbolAddress((void**)&vh, g_vh);
    cudaGetSymbolAddress((void**)&ath, g_ath);
    cudaGetSymbolAddress((void**)&wqkvh, g_wqkvh);
    cudaGetSymbolAddress((void**)&woh, g_woh); cudaGetSymbolAddress((void**)&wol, g_wol);
    cudaGetSymbolAddress((void**)&wath, g_wath);
    cudaGetSymbolAddress((void**)&wch, g_wch);
    cudaGetSymbolAddress((void**)&bqkvp, g_bqkv);
    cudaGetSymbolAddress((void**)&bcp, g_bc);

    cudaFuncSetAttribute(attn_h1,
                         cudaFuncAttributeMaxDynamicSharedMemorySize, ATTN_SMEM);
    cudaFuncSetAttribute(gemm_qkv_wc,
                         cudaFuncAttributeMaxDynamicSharedMemorySize, SM_COMB);
    cudaFuncSetAttribute(gemm_fin,
                         cudaFuncAttributeMaxDynamicSharedMemorySize, SM_FIN);

    prep_all<<<(ROWS*H + 255)/256, 256>>>(x, Wq, Wk, Wv, Wo, bq, bk, bv, bs);
    avgT_split<<<dim3(32, 32), dim3(32, 8)>>>(Ws);
    bc_kernel<<<H/8, 256>>>(Wo, bo);

    // fused QKV + Wc: 768 QKV tiles + 64 Wc tiles in one 832-CTA launch
    gemm_qkv_wc<<<dim3(26, 32), 256, SM_COMB>>>(
        xh, wqkvh, bqkvp, woh, wol, wath, qh, kh, vh, wch);

    attn_h1<<<dim3(SEQ/128, NHEADS, BATCH), 256, ATTN_SMEM>>>(qh, kh, vh, ath);

    gemm_fin<<<dim3(H/128, ROWS/128), 256, SM_FIN>>>(
        ath, wch, bcp, (float*)d_out, ROWS, H, H);
}

// round 16
// speedup vs baseline: 1.0791x; 1.0734x over previous
#include <cuda_runtime.h>
#include <cuda_fp16.h>
#include <math.h>
#include <stdint.h>

#define H 1024
#define NHEADS 16
#define HD 64
#define SEQ 2048
#define BATCH 2
#define ROWS (BATCH*SEQ)   // 4096

// ---------------- scratch (device globals; allocation-free) ----------------
__device__ __half g_xh[ROWS*H];
__device__ __half g_qh[ROWS*H];
__device__ __half g_kh[ROWS*H];
__device__ __half g_vh[ROWS*H];
__device__ __half g_ath[ROWS*H];
__device__ __half g_wqkvh[3*H*H];          // packed 0.125*Wq|Wk|Wv, hi only
__device__ __half g_woh[H*H], g_wol[H*H];  // Wo split (A of Wc GEMM)
__device__ __half g_wath[H*H];             // mean(Ws)^T hi only
__device__ __half g_wch[H*H];              // Wc = Wo @ Wa, hi only
__device__ float g_wcp[4*H*H];             // split-K partials for Wc
__device__ float g_bqkv[3*H];              // 0.125*bq | bk | bv
__device__ float g_bavg[H];
__device__ float g_bc[H];

// ---------------------------------------------------------------------------
__device__ __forceinline__ unsigned smaddr(const void* p) {
    return (unsigned)__cvta_generic_to_shared(p);
}
__device__ __forceinline__ void ldsm4(unsigned& r0, unsigned& r1, unsigned& r2,
                                      unsigned& r3, unsigned a) {
    asm volatile("ldmatrix.sync.aligned.m8n8.x4.shared.b16 {%0,%1,%2,%3}, [%4];"
                 : "=r"(r0), "=r"(r1), "=r"(r2), "=r"(r3) : "r"(a));
}
__device__ __forceinline__ void ldsm4t(unsigned& r0, unsigned& r1, unsigned& r2,
                                       unsigned& r3, unsigned a) {
    asm volatile("ldmatrix.sync.aligned.m8n8.x4.trans.shared.b16 {%0,%1,%2,%3}, [%4];"
                 : "=r"(r0), "=r"(r1), "=r"(r2), "=r"(r3) : "r"(a));
}
__device__ __forceinline__ void mma16h(float* c, const unsigned* a, const unsigned* b) {
    asm volatile(
        "mma.sync.aligned.m16n8k16.row.col.f32.f16.f16.f32 "
        "{%0,%1,%2,%3}, {%4,%5,%6,%7}, {%8,%9}, {%0,%1,%2,%3};"
        : "+f"(c[0]), "+f"(c[1]), "+f"(c[2]), "+f"(c[3])
        : "r"(a[0]), "r"(a[1]), "r"(a[2]), "r"(a[3]), "r"(b[0]), "r"(b[1]));
}
__device__ __forceinline__ void cpa16(unsigned dst, const void* src) {
    asm volatile("cp.async.ca.shared.global [%0], [%1], 16;" :: "r"(dst), "l"(src));
}
__device__ __forceinline__ unsigned pack2h(float x0, float x1) {
    __half h0 = __float2half_rn(x0), h1 = __float2half_rn(x1);
    return ((unsigned)__half_as_ushort(h1) << 16) | __half_as_ushort(h0);
}

// ---------------------------------------------------------------------------
// fused prep
// ---------------------------------------------------------------------------
__global__ void prep_all(const float* __restrict__ x,
                         const float* __restrict__ Wq, const float* __restrict__ Wk,
                         const float* __restrict__ Wv, const float* __restrict__ Wo,
                         const float* __restrict__ bq, const float* __restrict__ bk,
                         const float* __restrict__ bv, const float* __restrict__ bs)
{
    int i = blockIdx.x * 256 + threadIdx.x;
    if (i < ROWS*H) g_xh[i] = __float2half_rn(x[i]);
    if (i < H*H) {
        g_wqkvh[i]         = __float2half_rn(Wq[i] * 0.125f);
        g_wqkvh[H*H + i]   = __float2half_rn(Wk[i]);
        g_wqkvh[2*H*H + i] = __float2half_rn(Wv[i]);
        float w = Wo[i];
        __half h = __float2half_rn(w);
        g_woh[i] = h;
        g_wol[i] = __float2half_rn(w - __half2float(h));
    }
    if (i < H) {
        g_bqkv[i]       = bq[i] * 0.125f;
        g_bqkv[H + i]   = bk[i];
        g_bqkv[2*H + i] = bv[i];
        g_bavg[i] = (bs[i] + bs[i + H] + bs[i + 2*H]) * (1.0f/3.0f);
    }
}
__global__ void avgT_split(const float* __restrict__ Ws)
{
    __shared__ float tile[32][33];
    int j0 = blockIdx.x * 32, h0 = blockIdx.y * 32;
    int tx = threadIdx.x, ty = threadIdx.y;
    #pragma unroll
    for (int dy = 0; dy < 32; dy += 8) {
        int j = j0 + ty + dy, h = h0 + tx;
        tile[ty + dy][tx] = (Ws[j*H + h] + Ws[H*H + j*H + h] + Ws[2*H*H + j*H + h])
                            * (1.0f/3.0f);
    }
    __syncthreads();
    #pragma unroll
    for (int dy = 0; dy < 32; dy += 8) {
        int h = h0 + ty + dy, j = j0 + tx;
        g_wath[h*H + j] = __float2half_rn(tile[tx][ty + dy]);
    }
}
__global__ void bc_kernel(const float* __restrict__ Wo, const float* __restrict__ bo)
{
    int g = blockIdx.x * 8 + (threadIdx.x >> 5);
    int lane = threadIdx.x & 31;
    const float* wr = Wo + (size_t)g * H;
    float s0 = 0.f, s1 = 0.f, s2 = 0.f, s3 = 0.f;
    #pragma unroll
    for (int j = 0; j < H; j += 128) {
        s0 += wr[j + lane]      * g_bavg[j + lane];
        s1 += wr[j + lane + 32] * g_bavg[j + lane + 32];
        s2 += wr[j + lane + 64] * g_bavg[j + lane + 64];
        s3 += wr[j + lane + 96] * g_bavg[j + lane + 96];
    }
    float s = (s0 + s1) + (s2 + s3);
    #pragma unroll
    for (int o = 16; o; o >>= 1) s += __shfl_xor_sync(0xffffffffu, s, o);
    if (lane == 0) g_bc[g] = s + bo[g];
}
// wch = fp16(sum of 4 split-K partials)
__global__ void wc_reduce()
{
    int i = blockIdx.x * 256 + threadIdx.x;
    if (i < H*H)
        g_wch[i] = __float2half_rn(g_wcp[i] + g_wcp[H*H + i] +
                                   g_wcp[2*H*H + i] + g_wcp[3*H*H + i]);
}

// ---------------------------------------------------------------------------
// GEMM: C = A[M,K] @ Bhi[N,K]^T + bias.  AP = A passes (1: hi, 2: hi+lo).
// BM=BN=128, BK=32, 256 thr, 2-stage cp.async, (AP+1) arrays/stage.
// OUTMODE 0: fp32 C.  1: fp16 Ohi.  2: QKV band routing.
// ---------------------------------------------------------------------------
#define GSTR 20
#define GARR (128*GSTR)
template<int OUTMODE, int AP>
__global__ __launch_bounds__(256, 2) void gemm_sp(
    const __half* __restrict__ Ahi, const __half* __restrict__ Alo,
    const __half* __restrict__ Bhi,
    const float* __restrict__ bias,
    float* __restrict__ C,
    __half* __restrict__ Ohi,
    __half* __restrict__ Khi,  __half* __restrict__ Vhi,
    int M, int N, int K)
{
    extern __shared__ unsigned gsm[];
    const int NARR = AP + 1;
    const int t = threadIdx.x, lane = t & 31, warp = t >> 5;
    const int wm = (warp >> 2) * 64, wn = (warp & 3) * 32;
    const int m0 = blockIdx.y * 128, n0 = blockIdx.x * 128;

    float acc[16][4];
    #pragma unroll
    for (int i = 0; i < 16; i++)
        #pragma unroll
        for (int j = 0; j < 4; j++) acc[i][j] = 0.0f;

    const int lr = t >> 1, half = t & 1;
    const size_t arow = (size_t)(m0 + lr) * K + half * 16;
    const size_t brow = (size_t)(n0 + lr) * K + half * 16;
    const int sw = lr * GSTR + half * 8;
    const int NB = K / 32;

    auto fill = [&](int st, int bi) {
        unsigned* B0 = gsm + st * NARR * GARR;
        size_t ko = (size_t)bi * 32;
        cpa16(smaddr(&B0[0*GARR + sw]),     Ahi + arow + ko);
        cpa16(smaddr(&B0[0*GARR + sw + 4]), Ahi + arow + ko + 8);
        if (AP == 2) {
            cpa16(smaddr(&B0[1*GARR + sw]),     Alo + arow + ko);
            cpa16(smaddr(&B0[1*GARR + sw + 4]), Alo + arow + ko + 8);
        }
        cpa16(smaddr(&B0[(NARR-1)*GARR + sw]),     Bhi + brow + ko);
        cpa16(smaddr(&B0[(NARR-1)*GARR + sw + 4]), Bhi + brow + ko + 8);
        asm volatile("cp.async.commit_group;");
    };

    fill(0, 0);

    for (int bi = 0; bi < NB; bi++) {
        if (bi + 1 < NB) {
            fill((bi + 1) & 1, bi + 1);
            asm volatile("cp.async.wait_group 1;");
        } else {
            asm volatile("cp.async.wait_group 0;");
        }
        __syncthreads();

        unsigned* Ah = gsm + (bi & 1) * NARR * GARR;
        unsigned* Al = Ah + GARR;
        unsigned* Bh = Ah + (NARR-1)*GARR;

        #pragma unroll
        for (int ks = 0; ks < 2; ks++) {
            const int ar = ((lane >> 3) & 1) * 8 + (lane & 7);
            const int aw = ks * 8 + (lane >> 4) * 4;
            unsigned ah[4][4], am[4][4];
            #pragma unroll
            for (int mt = 0; mt < 4; mt++) {
                int r = (wm + mt*16 + ar) * GSTR + aw;
                ldsm4(ah[mt][0], ah[mt][1], ah[mt][2], ah[mt][3], smaddr(&Ah[r]));
                if (AP == 2)
                    ldsm4(am[mt][0], am[mt][1], am[mt][2], am[mt][3], smaddr(&Al[r]));
            }
            const int br = ((lane >> 4) & 1) * 8 + (lane & 7);
            const int bw = ks * 8 + ((lane >> 3) & 1) * 4;
            unsigned bh[2][4];
            #pragma unroll
            for (int np = 0; np < 2; np++) {
                int r = (wn + np*16 + br) * GSTR + bw;
                ldsm4(bh[np][0], bh[np][1], bh[np][2], bh[np][3], smaddr(&Bh[r]));
            }
            #pragma unroll
            for (int mt = 0; mt < 4; mt++)
                #pragma unroll
                for (int nt = 0; nt < 4; nt++) {
                    unsigned* bhp = &bh[nt >> 1][(nt & 1) * 2];
                    mma16h(acc[mt*4+nt], ah[mt], bhp);
                    if (AP == 2) mma16h(acc[mt*4+nt], am[mt], bhp);
                }
        }
        __syncthreads();
    }

    #pragma unroll
    for (int mt = 0; mt < 4; mt++) {
        int row = m0 + wm + mt*16 + (lane >> 2);
        #pragma unroll
        for (int nt = 0; nt < 4; nt++) {
            int col = n0 + wn + nt*8 + (lane & 3) * 2;
            float b0 = __ldg(bias + col), b1 = __ldg(bias + col + 1);
            float* a = acc[mt*4+nt];
            float v00 = a[0] + b0, v01 = a[1] + b1;
            float v10 = a[2] + b0, v11 = a[3] + b1;
            if (OUTMODE == 0) {
                float2 u;
                u.x = v00; u.y = v01; *(float2*)(C + (size_t)row * N + col) = u;
                u.x = v10; u.y = v11; *(float2*)(C + (size_t)(row + 8) * N + col) = u;
            } else if (OUTMODE == 1) {
                *(unsigned*)(Ohi + (size_t)row * N + col)       = pack2h(v00, v01);
                *(unsigned*)(Ohi + (size_t)(row + 8) * N + col) = pack2h(v10, v11);
            } else {
                int which = n0 >> 10;
                int cl = col & 1023;
                __half* dst = (which == 0) ? Ohi : ((which == 1) ? Khi : Vhi);
                *(unsigned*)(dst + (size_t)row * H + cl)       = pack2h(v00, v01);
                *(unsigned*)(dst + (size_t)(row + 8) * H + cl) = pack2h(v10, v11);
            }
        }
    }
}

// ---------------------------------------------------------------------------
// Split-K Wc GEMM: partial[kz] = (woh+wol)[:, kz*256:(kz+1)*256] @ wath^T slice
// grid (8, 8, 4); fp32 partials. 2-pass A, BK=32, 2-stage, 3 arrays.
// ---------------------------------------------------------------------------
__global__ __launch_bounds__(256, 2) void gemm_wc_sk()
{
    extern __shared__ unsigned gsm[];
    const int t = threadIdx.x, lane = t & 31, warp = t >> 5;
    const int wm = (warp >> 2) * 64, wn = (warp & 3) * 32;
    const int m0 = blockIdx.y * 128, n0 = blockIdx.x * 128;
    const int kz = blockIdx.z;
    const int K = H;

    float acc[16][4];
    #pragma unroll
    for (int i = 0; i < 16; i++)
        #pragma unroll
        for (int j = 0; j < 4; j++) acc[i][j] = 0.0f;

    const int lr = t >> 1, half = t & 1;
    const size_t arow = (size_t)(m0 + lr) * K + kz * 256 + half * 16;
    const size_t brow = (size_t)(n0 + lr) * K + kz * 256 + half * 16;
    const int sw = lr * GSTR + half * 8;
    const int NB = 256 / 32;   // 8

    auto fill = [&](int st, int bi) {
        unsigned* B0 = gsm + st * 3 * GARR;
        size_t ko = (size_t)bi * 32;
        cpa16(smaddr(&B0[0*GARR + sw]),     g_woh + arow + ko);
        cpa16(smaddr(&B0[0*GARR + sw + 4]), g_woh + arow + ko + 8);
        cpa16(smaddr(&B0[1*GARR + sw]),     g_wol + arow + ko);
        cpa16(smaddr(&B0[1*GARR + sw + 4]), g_wol + arow + ko + 8);
        cpa16(smaddr(&B0[2*GARR + sw]),     g_wath + brow + ko);
        cpa16(smaddr(&B0[2*GARR + sw + 4]), g_wath + brow + ko + 8);
        asm volatile("cp.async.commit_group;");
    };

    fill(0, 0);

    for (int bi = 0; bi < NB; bi++) {
        if (bi + 1 < NB) {
            fill((bi + 1) & 1, bi + 1);
            asm volatile("cp.async.wait_group 1;");
        } else {
            asm volatile("cp.async.wait_group 0;");
        }
        __syncthreads();

        unsigned* Ah = gsm + (bi & 1) * 3 * GARR;
        unsigned* Al = Ah + GARR;
        unsigned* Bh = Ah + 2*GARR;

        #pragma unroll
        for (int ks = 0; ks < 2; ks++) {
            const int ar = ((lane >> 3) & 1) * 8 + (lane & 7);
            const int aw = ks * 8 + (lane >> 4) * 4;
            unsigned ah[4][4], am[4][4];
            #pragma unroll
            for (int mt = 0; mt < 4; mt++) {
                int r = (wm + mt*16 + ar) * GSTR + aw;
                ldsm4(ah[mt][0], ah[mt][1], ah[mt][2], ah[mt][3], smaddr(&Ah[r]));
                ldsm4(am[mt][0], am[mt][1], am[mt][2], am[mt][3], smaddr(&Al[r]));
            }
            const int br = ((lane >> 4) & 1) * 8 + (lane & 7);
            const int bw = ks * 8 + ((lane >> 3) & 1) * 4;
            unsigned bh[2][4];
            #pragma unroll
            for (int np = 0; np < 2; np++) {
                int r = (wn + np*16 + br) * GSTR + bw;
                ldsm4(bh[np][0], bh[np][1], bh[np][2], bh[np][3], smaddr(&Bh[r]));
            }
            #pragma unroll
            for (int mt = 0; mt < 4; mt++)
                #pragma unroll
                for (int nt = 0; nt < 4; nt++) {
                    unsigned* bhp = &bh[nt >> 1][(nt & 1) * 2];
                    mma16h(acc[mt*4+nt], ah[mt], bhp);
                    mma16h(acc[mt*4+nt], am[mt], bhp);
                }
        }
        __syncthreads();
    }

    float* out = g_wcp + (size_t)kz * H * H;
    #pragma unroll
    for (int mt = 0; mt < 4; mt++) {
        int row = m0 + wm + mt*16 + (lane >> 2);
        #pragma unroll
        for (int nt = 0; nt < 4; nt++) {
            int col = n0 + wn + nt*8 + (lane & 3) * 2;
            float* a = acc[mt*4+nt];
            float2 u;
            u.x = a[0]; u.y = a[1];
            *(float2*)(out + (size_t)row * H + col) = u;
            u.x = a[2]; u.y = a[3];
            *(float2*)(out + (size_t)(row + 8) * H + col) = u;
        }
    }
}

// ---------------------------------------------------------------------------
// Flash attention, all-fp16, BQ=128, double-buffered KV (R12 proven config).
// ---------------------------------------------------------------------------
#define ASTR 36
#define TILE_W (64*ASTR)
#define ATTN_SMEM (4*TILE_W*4)  // 36864 B

__global__ __launch_bounds__(256, 2) void attn_h1(
    const __half* __restrict__ qhi,
    const __half* __restrict__ khi, const __half* __restrict__ vhi,
    __half* __restrict__ athi)
{
    extern __shared__ unsigned smu[];
    unsigned* bufs = smu;

    const int t = threadIdx.x, lane = t & 31, warp = t >> 5;
    const int qb = blockIdx.x, h = blockIdx.y, b = blockIdx.z;
    const int NT = SEQ / 64;

    const int krow = t >> 2, kcb = t & 3;
    const unsigned kd0 = krow * ASTR + kcb * 8;

    {
        const int qrow = t >> 1, qhf = t & 1;
        size_t qoff = ((size_t)(b*SEQ + qb*128 + qrow)) * H + h*HD + qhf*32;
        unsigned d = 2*TILE_W + qrow * ASTR + qhf * 16;
        #pragma unroll
        for (int i = 0; i < 4; i++)
            cpa16(smaddr(&bufs[d + i*4]), qhi + qoff + i*8);
        asm volatile("cp.async.commit_group;");
    }
    {
        size_t base = ((size_t)(b*SEQ + krow)) * H + h*HD + kcb*16;
        cpa16(smaddr(&bufs[0*TILE_W + kd0]),     khi + base);
        cpa16(smaddr(&bufs[0*TILE_W + kd0 + 4]), khi + base + 8);
        cpa16(smaddr(&bufs[1*TILE_W + kd0]),     vhi + base);
        cpa16(smaddr(&bufs[1*TILE_W + kd0 + 4]), vhi + base + 8);
        asm volatile("cp.async.commit_group;");
    }

    asm volatile("cp.async.wait_group 1;");
    __syncthreads();

    unsigned qfr[4][4];
    {
        const int ar = warp*16 + ((lane >> 3) & 1) * 8 + (lane & 7);
        #pragma unroll
        for (int ks = 0; ks < 4; ks++) {
            int w = ks * 8 + (lane >> 4) * 4;
            ldsm4(qfr[ks][0], qfr[ks][1], qfr[ks][2], qfr[ks][3],
                  smaddr(&bufs[2*TILE_W + ar*ASTR + w]));
        }
    }
    __syncthreads();

    float o[8][4];
    #pragma unroll
    for (int i = 0; i < 8; i++)
        #pragma unroll
        for (int j = 0; j < 4; j++) o[i][j] = 0.0f;
    float m0 = -1e30f, m1 = -1e30f, l0 = 0.0f, l1 = 0.0f;
    const int r = warp*16 + (lane >> 2);

    for (int kb = 0; kb < NT; kb++) {
        if (kb + 1 < NT) {
            size_t base = ((size_t)(b*SEQ + (kb+1)*64 + krow)) * H + h*HD + kcb*16;
            unsigned* Bn = bufs + ((kb+1) & 1) * 2 * TILE_W;
            cpa16(smaddr(&Bn[0*TILE_W + kd0]),     khi + base);
            cpa16(smaddr(&Bn[0*TILE_W + kd0 + 4]), khi + base + 8);
            cpa16(smaddr(&Bn[1*TILE_W + kd0]),     vhi + base);
            cpa16(smaddr(&Bn[1*TILE_W + kd0 + 4]), vhi + base + 8);
            asm volatile("cp.async.commit_group;");
            asm volatile("cp.async.wait_group 1;");
        } else {
            asm volatile("cp.async.wait_group 0;");
        }
        __syncthreads();

        unsigned* Kh = bufs + (kb & 1) * 2 * TILE_W;
        unsigned* Vh = Kh + TILE_W;

        float s[8][4];
        #pragma unroll
        for (int i = 0; i < 8; i++)
            #pragma unroll
            for (int j = 0; j < 4; j++) s[i][j] = 0.0f;

        #pragma unroll
        for (int ks = 0; ks < 4; ks++) {
            const int br = ((lane >> 4) & 1) * 8 + (lane & 7);
            const int bw = ks * 8 + ((lane >> 3) & 1) * 4;
            unsigned bh[4][4];
            #pragma unroll
            for (int np = 0; np < 4; np++) {
                int rr = (np*16 + br) * ASTR + bw;
                ldsm4(bh[np][0], bh[np][1], bh[np][2], bh[np][3], smaddr(&Kh[rr]));
            }
            #pragma unroll
            for (int nt = 0; nt < 8; nt++)
                mma16h(s[nt], qfr[ks], &bh[nt >> 1][(nt & 1) * 2]);
        }

        float mx0 = -1e30f, mx1 = -1e30f;
        #pragma unroll
        for (int nt = 0; nt < 8; nt++) {
            mx0 = fmaxf(mx0, fmaxf(s[nt][0], s[nt][1]));
            mx1 = fmaxf(mx1, fmaxf(s[nt][2], s[nt][3]));
        }
        mx0 = fmaxf(mx0, __shfl_xor_sync(0xffffffffu, mx0, 1));
        mx0 = fmaxf(mx0, __shfl_xor_sync(0xffffffffu, mx0, 2));
        mx1 = fmaxf(mx1, __shfl_xor_sync(0xffffffffu, mx1, 1));
        mx1 = fmaxf(mx1, __shfl_xor_sync(0xffffffffu, mx1, 2));
        float nm0 = fmaxf(m0, mx0), nm1 = fmaxf(m1, mx1);
        float a0 = __expf(m0 - nm0), a1 = __expf(m1 - nm1);

        float sum0 = 0.0f, sum1 = 0.0f;
        #pragma unroll
        for (int nt = 0; nt < 8; nt++) {
            s[nt][0] = __expf(s[nt][0] - nm0); sum0 += s[nt][0];
            s[nt][1] = __expf(s[nt][1] - nm0); sum0 += s[nt][1];
            s[nt][2] = __expf(s[nt][2] - nm1); sum1 += s[nt][2];
            s[nt][3] = __expf(s[nt][3] - nm1); sum1 += s[nt][3];
        }
        sum0 += __shfl_xor_sync(0xffffffffu, sum0, 1);
        sum0 += __shfl_xor_sync(0xffffffffu, sum0, 2);
        sum1 += __shfl_xor_sync(0xffffffffu, sum1, 1);
        sum1 += __shfl_xor_sync(0xffffffffu, sum1, 2);
        l0 = l0*a0 + sum0;  l1 = l1*a1 + sum1;
        m0 = nm0;           m1 = nm1;
        #pragma unroll
        for (int nt = 0; nt < 8; nt++) {
            o[nt][0] *= a0; o[nt][1] *= a0;
            o[nt][2] *= a1; o[nt][3] *= a1;
        }

        #pragma unroll
        for (int ks = 0; ks < 4; ks++) {
            unsigned ph[4];
            ph[0] = pack2h(s[2*ks][0],   s[2*ks][1]);
            ph[1] = pack2h(s[2*ks][2],   s[2*ks][3]);
            ph[2] = pack2h(s[2*ks+1][0], s[2*ks+1][1]);
            ph[3] = pack2h(s[2*ks+1][2], s[2*ks+1][3]);

            const int vr = ks*16 + ((lane >> 3) & 1) * 8 + (lane & 7);
            unsigned vh[4][4];
            #pragma unroll
            for (int np = 0; np < 4; np++) {
                int vw = np*8 + (lane >> 4) * 4;
                ldsm4t(vh[np][0], vh[np][1], vh[np][2], vh[np][3], smaddr(&Vh[vr*ASTR + vw]));
            }
            #pragma unroll
            for (int nt = 0; nt < 8; nt++)
                mma16h(o[nt], ph, &vh[nt >> 1][(nt & 1) * 2]);
        }
        __syncthreads();
    }

    float inv0 = 1.0f / l0, inv1 = 1.0f / l1;
    size_t gr0 = (size_t)(b*SEQ + qb*128 + r) * H + h*HD;
    size_t gr1 = (size_t)(b*SEQ + qb*128 + r + 8) * H + h*HD;
    int col = (lane & 3) * 2;
    #pragma unroll
    for (int nt = 0; nt < 8; nt++) {
        *(unsigned*)(athi + gr0 + nt*8 + col) = pack2h(o[nt][0]*inv0, o[nt][1]*inv0);
        *(unsigned*)(athi + gr1 + nt*8 + col) = pack2h(o[nt][2]*inv1, o[nt][3]*inv1);
    }
}

// ---------------------------------------------------------------------------
extern "C" void kernel_launch(void* const* d_in, const int* in_sizes, int n_in,
                              void* d_out, int out_size)
{
    const float* x  = (const float*)d_in[0];
    const float* Wq = (const float*)d_in[1];
    const float* bq = (const float*)d_in[2];
    const float* Wk = (const float*)d_in[3];
    const float* bk = (const float*)d_in[4];
    const float* Wv = (const float*)d_in[5];
    const float* bv = (const float*)d_in[6];
    const float* Ws = (const float*)d_in[7];
    const float* bs = (const float*)d_in[8];
    const float* Wo = (const float*)d_in[9];
    const float* bo = (const float*)d_in[10];

    __half *xh, *qh, *kh, *vh, *ath;
    __half *wqkvh, *wch;
    float *bqkvp, *bcp;
    cudaGetSymbolAddress((void**)&xh, g_xh);
    cudaGetSymbolAddress((void**)&qh, g_qh);
    cudaGetSymbolAddress((void**)&kh, g_kh);
    cudaGetSymbolAddress((void**)&vh, g_vh);
    cudaGetSymbolAddress((void**)&ath, g_ath);
    cudaGetSymbolAddress((void**)&wqkvh, g_wqkvh);
    cudaGetSymbolAddress((void**)&wch, g_wch);
    cudaGetSymbolAddress((void**)&bqkvp, g_bqkv);
    cudaGetSymbolAddress((void**)&bcp, g_bc);

    const int SM1 = 2*2*GARR*4;   // AP=1: 40960 B
    const int SM3 = 2*3*GARR*4;   // split-K Wc: 61440 B
    cudaFuncSetAttribute(attn_h1,
                         cudaFuncAttributeMaxDynamicSharedMemorySize, ATTN_SMEM);
    cudaFuncSetAttribute(gemm_sp<0,1>,
                         cudaFuncAttributeMaxDynamicSharedMemorySize, SM1);
    cudaFuncSetAttribute(gemm_sp<2,1>,
                         cudaFuncAttributeMaxDynamicSharedMemorySize, SM1);
    cudaFuncSetAttribute(gemm_wc_sk,
                         cudaFuncAttributeMaxDynamicSharedMemorySize, SM3);

    prep_all<<<(ROWS*H + 255)/256, 256>>>(x, Wq, Wk, Wv, Wo, bq, bk, bv, bs);
    avgT_split<<<dim3(32, 32), dim3(32, 8)>>>(Ws);
    bc_kernel<<<H/8, 256>>>(Wo, bo);

    // split-K Wc: 256 CTAs (near-full wave)
    gemm_wc_sk<<<dim3(8, 8, 4), 256, SM3>>>();
    wc_reduce<<<(H*H + 255)/256, 256>>>();

    // fused QKV (single-pass A): [4096, 3072]
    gemm_sp<2,1><<<dim3(3*H/128, ROWS/128), 256, SM1>>>(
        xh, nullptr, wqkvh, bqkvp,
        nullptr, qh, kh, vh, ROWS, 3*H, H);

    attn_h1<<<dim3(SEQ/128, NHEADS, BATCH), 256, ATTN_SMEM>>>(qh, kh, vh, ath);

    // out = att @ Wc^T + bc (single-pass A)
    gemm_sp<0,1><<<dim3(H/128, ROWS/128), 256, SM1>>>(
        ath, nullptr, wch, bcp,
        (float*)d_out, nullptr, nullptr, nullptr, ROWS, H, H);
}